// round 14
// baseline (speedup 1.0000x reference)
#include <cuda_runtime.h>
#include <math.h>

#define NELEM 16384
#define NB    16384
#define NBLK  128
#define NTHR  128
#define CAP   16
#define NCHK  512            // 512 chunks of 32 buckets -> 32 adds/counter max
#define CS    64             // 64 floats = 256B stride between chunk counters
#define BSLOT 8              // 8-way split barrier / tail accumulators
#define USTRIDE 32           // 32 ull = 256B stride
#define NUM_SCALE 262144.0f  // 2^18 fixed-point scale for num
#define NUM_BIAS  (1LL << 31)

typedef unsigned long long ull;

// Parity-double-buffered / monotone scratch: replay-safe, no cleanup barrier.
__device__ float    g_bsum[2][NB];            // bucket sums (atomicAdd, ~1 add/addr)
__device__ unsigned g_cnt[2][NB];             // bucket slot counts (atomicAdd)
__device__ float4   g_slot[NB * CAP];         // (time, exp, event, 0) — tie lists
__device__ float    g_csum[2][NCHK * CS];     // chunk totals (atomicAdd, 32 adds/addr)
__device__ ull      g_barx[BSLOT * USTRIDE];  // monotone barrier: 16 adds/slot/launch
__device__ ull      g_accx[2][BSLOT * USTRIDE]; // packed tail: count|den|biased num
__device__ ull      g_wfin;                   // winner ticket: +8 per launch (monotone)
__device__ ull      g_done;                   // epoch: +1 per launch (winner only)

static __device__ __forceinline__ ull ldv64(const ull* p) {
    ull v; asm volatile("ld.global.cg.u64 %0, [%1];" : "=l"(v) : "l"(p)); return v;
}
static __device__ __forceinline__ unsigned ldv32(const unsigned* p) {
    unsigned v; asm volatile("ld.global.cg.u32 %0, [%1];" : "=r"(v) : "l"(p)); return v;
}
static __device__ __forceinline__ float ldvf(const float* p) {
    float v; asm volatile("ld.global.cg.f32 %0, [%1];" : "=f"(v) : "l"(p)); return v;
}

static __device__ __forceinline__ int bucket_of(float t) {
    int b = (int)(t * 16384.0f);
    return b < 0 ? 0 : (b > NB - 1 ? NB - 1 : b);
}

__global__ void __launch_bounds__(NTHR, 1) cox_kernel(
    const float* __restrict__ risk,
    const float* __restrict__ time,
    const float* __restrict__ event,
    float* __restrict__ out)
{
    const int t   = threadIdx.x;
    const int blk = blockIdx.x;
    const int i   = blk * NTHR + t;
    const int lane = t & 31, w = t >> 5;

    __shared__ float s_w[4];
    __shared__ float s_base;
    __shared__ float rn[4], rd[4];

    // ---- Front: quiescent epoch + inputs, all loads concurrent ------------
    const unsigned ep1 = (unsigned)ldv64(&g_done) + 1u;
    const int par = (int)(ep1 & 1u);
    const float my_t  = __ldg(&time[i]);
    const float my_ev = __ldg(&event[i]);
    const float my_e  = __expf(__ldg(&risk[i]));
    const int   b     = bucket_of(my_t);

    // ---- Phase 1: histogram + chunk totals + slot scatter ------------------
    atomicAdd(&g_bsum[par][b], my_e);                 // ~1 add per address
    atomicAdd(&g_csum[par][(b >> 5) * CS], my_e);     // ≤~32 adds per address
    unsigned c = atomicAdd(&g_cnt[par][b], 1u);
    if (c < CAP) g_slot[b * CAP + c] = make_float4(my_t, my_e, my_ev, 0.0f);

    // ---- B1: 8-way split monotone barrier ----------------------------------
    __threadfence();                                   // drain my stores/atomics
    __syncthreads();
    if (t == 0) atomicAdd(&g_barx[(blk & 7) * USTRIDE], 1ULL);
    if (w == 0) {
        if (lane < BSLOT) {
            const ull target = (ull)ep1 * (ull)(NBLK / BSLOT);
            while (ldv64(&g_barx[lane * USTRIDE]) < target) { }
        }
        __syncwarp();
    }
    __syncthreads();
    __threadfence();

    // ---- Phase 2: owner of bucket i; all loads issued up front (MLP) ------
    const float    bs  = ldvf(&g_bsum[par][i]);
    const unsigned cnt = ldv32(&g_cnt[par][i]);
    float4 sl0 = __ldcg(&g_slot[i * CAP + 0]);
    float4 sl1 = __ldcg(&g_slot[i * CAP + 1]);
    float4 sl2 = __ldcg(&g_slot[i * CAP + 2]);
    float4 sl3 = __ldcg(&g_slot[i * CAP + 3]);

    // Warp 0 gathers all 512 chunk totals (16 loads/lane, parallel) and
    // computes base = sum over chunks strictly above this block's range.
    if (w == 0) {
        const int c0 = blk * 4 + 4;                   // first chunk above my block
        float th = 0.0f;
        #pragma unroll
        for (int k = 0; k < 16; k++) {
            int ch = lane + 32 * k;
            float cv = ldvf(&g_csum[par][ch * CS]);
            if (ch >= c0) th += cv;
        }
        #pragma unroll
        for (int o = 16; o > 0; o >>= 1) th += __shfl_down_sync(0xffffffffu, th, o);
        if (lane == 0) s_base = th;
    }

    // Next-epoch zeroing — post-barrier, off the critical path.
    g_bsum[par ^ 1][i] = 0.0f;
    g_cnt[par ^ 1][i]  = 0u;
    if (i < NCHK) g_csum[par ^ 1][i * CS] = 0.0f;
    if (blk == 0 && t < BSLOT) g_accx[par ^ 1][t * USTRIDE] = 0ULL;

    // In-warp inclusive suffix scan of bucket sums (within block's 128 buckets)
    float v = bs;
    #pragma unroll
    for (int d = 1; d < 32; d <<= 1) {
        float o = __shfl_down_sync(0xffffffffu, v, d);
        if (lane + d < 32) v += o;
    }
    if (lane == 0) s_w[w] = v;
    __syncthreads();
    float hiW = 0.0f;
    #pragma unroll
    for (int k = 0; k < 4; k++) if (k > w) hiW += s_w[k];
    const float sb = s_base + (v - bs) + hiW;          // sum over buckets strictly > i

    // ---- Phase 3: per-element loss for my bucket (exact in-bucket ties) ---
    float num = 0.0f, den = 0.0f;
    if (cnt <= 4u) {                                   // register fast path (99.6%)
        const int len = (int)cnt;
        float tt[4] = {sl0.x, sl1.x, sl2.x, sl3.x};
        float ee[4] = {sl0.y, sl1.y, sl2.y, sl3.y};
        float vv[4] = {sl0.z, sl1.z, sl2.z, sl3.z};
        #pragma unroll
        for (int a = 0; a < 4; a++) {
            if (a < len && vv[a] != 0.0f) {
                float s = sb;
                #pragma unroll
                for (int m = 0; m < 4; m++)
                    if (m < len && tt[m] >= tt[a]) s += ee[m];
                num += __logf(ee[a] / s);
                den += 1.0f;
            }
        }
    } else if (cnt <= CAP) {                           // gmem path (rare, exact)
        const int len = (int)cnt;
        for (int a = 0; a < len; a++) {
            float4 pa = __ldcg(&g_slot[i * CAP + a]);
            if (pa.z != 0.0f) {
                float s = sb;
                for (int m = 0; m < len; m++) {
                    float4 pm = __ldcg(&g_slot[i * CAP + m]);
                    if (pm.x >= pa.x) s += pm.y;
                }
                num += __logf(pa.y / s);
                den += 1.0f;
            }
        }
    } else {                                           // overflow fallback (exact)
        for (int j = 0; j < NELEM; j++) {
            float tj = __ldg(&time[j]);
            if (bucket_of(tj) == i && __ldg(&event[j]) != 0.0f) {
                float s = sb;
                for (int m2 = 0; m2 < NELEM; m2++) {
                    float tm = __ldg(&time[m2]);
                    if (bucket_of(tm) == i && tm >= tj) s += __expf(__ldg(&risk[m2]));
                }
                num += __ldg(&risk[j]) - __logf(s);
                den += 1.0f;
            }
        }
    }

    // ---- Block reduce -> 8-way split fused tail ----------------------------
    #pragma unroll
    for (int o = 16; o > 0; o >>= 1) {
        num += __shfl_down_sync(0xffffffffu, num, o);
        den += __shfl_down_sync(0xffffffffu, den, o);
    }
    if (lane == 0) { rn[w] = num; rd[w] = den; }
    __syncthreads();
    if (t == 0) {
        float n = rn[0] + rn[1] + rn[2] + rn[3];
        float d = rd[0] + rd[1] + rd[2] + rd[3];
        // Slot pack: [63:56] count (to 16), [55:41] den, [40:0] biased num_fx.
        long long nfx = llrintf(n * NUM_SCALE);
        ull mine = (1ULL << 56)
                 | ((ull)(unsigned)(d + 0.5f) << 41)
                 | (ull)(nfx + NUM_BIAS);
        ull* slot = &g_accx[par][(blk & 7) * USTRIDE];
        ull tot = atomicAdd(slot, mine) + mine;
        if ((tot >> 56) == (ull)(NBLK / BSLOT)) {      // my slot just became full
            ull wold = atomicAdd(&g_wfin, 1ULL);
            if (wold == (ull)ep1 * BSLOT - 1ULL) {     // 8th slot-finisher: winner
                long long tfx = 0; ull tden = 0;
                #pragma unroll
                for (int s8 = 0; s8 < BSLOT; s8++) {
                    ull sv = ldv64(&g_accx[par][s8 * USTRIDE]);
                    tfx  += (long long)(sv & ((1ULL << 41) - 1ULL));
                    tden += (sv >> 41) & 0x7FFFULL;
                }
                tfx -= (long long)NBLK * NUM_BIAS;
                out[0] = -((float)tfx * (1.0f / NUM_SCALE)) / (float)tden;
                atomicAdd(&g_done, 1ULL);              // bump epoch once
            }
        }
    }
}

extern "C" void kernel_launch(void* const* d_in, const int* in_sizes, int n_in,
                              void* d_out, int out_size) {
    const float* risk  = (const float*)d_in[0];
    const float* time  = (const float*)d_in[1];
    const float* event = (const float*)d_in[2];
    float* out = (float*)d_out;
    cox_kernel<<<NBLK, NTHR>>>(risk, time, event, out);
}

// round 15
// speedup vs baseline: 1.1550x; 1.1550x over previous
#include <cuda_runtime.h>
#include <math.h>

#define NELEM 16384
#define NB    16384
#define NBLK  128
#define NTHR  128
#define CAP   16
#define CSTRIDE 64            // 256B between chunk counters (distinct L2 slices)
#define NUM_SCALE 262144.0f   // 2^18 fixed-point scale for loss num
#define NUM_BIAS  (1LL << 31) // per-block bias so tail contributions are positive
#define E_SCALE   268435456.0f  // 2^28 fixed-point scale for exp sums
#define E_INV     (1.0f / 268435456.0f)

typedef unsigned long long ull;

// Parity-double-buffered / monotone scratch: replay-safe, no cleanup barrier.
__device__ ull      g_bc[2][NB];               // fused: [63:56] cnt | [55:0] exp_fx sum
__device__ float4   g_slot[NB * CAP];          // (time, exp, event, 0) — tie lists only
__device__ float    g_csum[2][NBLK * CSTRIDE]; // chunk totals (float atomicAdd, padded)
__device__ ull      g_acc[2];                  // fused tail: count|den|biased num (parity)
__device__ ull      g_bar;                     // monotone barrier counter: +NBLK per launch
__device__ ull      g_done;                    // epoch: +1 per launch (winner only)

static __device__ __forceinline__ ull ldv64(const ull* p) {
    ull v; asm volatile("ld.global.cg.u64 %0, [%1];" : "=l"(v) : "l"(p)); return v;
}
static __device__ __forceinline__ float ldvf(const float* p) {
    float v; asm volatile("ld.global.cg.f32 %0, [%1];" : "=f"(v) : "l"(p)); return v;
}

static __device__ __forceinline__ int bucket_of(float t) {
    int b = (int)(t * 16384.0f);
    return b < 0 ? 0 : (b > NB - 1 ? NB - 1 : b);
}

__global__ void __launch_bounds__(NTHR, 1) cox_kernel(
    const float* __restrict__ risk,
    const float* __restrict__ time,
    const float* __restrict__ event,
    float* __restrict__ out)
{
    const int t   = threadIdx.x;
    const int blk = blockIdx.x;
    const int i   = blk * NTHR + t;
    const int lane = t & 31, w = t >> 5;

    __shared__ float s_w[4];
    __shared__ float s_base;
    __shared__ float rn[4], rd[4];

    // ---- Front: quiescent epoch + inputs, all loads concurrent ------------
    const unsigned ep1 = (unsigned)ldv64(&g_done) + 1u;
    const int par = (int)(ep1 & 1u);
    const float my_t  = __ldg(&time[i]);
    const float my_ev = __ldg(&event[i]);
    const float my_e  = __expf(__ldg(&risk[i]));     // MUFU-direct
    const int   b     = bucket_of(my_t);

    // ---- Phase 1: ONE fused bucket atomic + chunk atomic + slot scatter ---
    const ull efx = (ull)llrintf(my_e * E_SCALE);    // < 2^35, field is 56 bits
    ull old = atomicAdd(&g_bc[par][b], (1ULL << 56) | efx);
    unsigned c = (unsigned)(old >> 56);              // my slot index in bucket
    atomicAdd(&g_csum[par][(b >> 7) * CSTRIDE], my_e); // chunk total, final pre-B1
    if (c < CAP) g_slot[b * CAP + c] = make_float4(my_t, my_e, my_ev, 0.0f);

    // ---- B1: single monotone-counter grid barrier (R13-proven) ------------
    __threadfence();                                  // drain slot store + atomics
    __syncthreads();
    if (t == 0) {
        atomicAdd(&g_bar, 1ULL);
        const ull target = (ull)ep1 * (ull)NBLK;
        while (ldv64(&g_bar) < target) { }
        __threadfence();
    }
    __syncthreads();

    // ---- Phase 2: owner of bucket i; all loads issued up front (MLP) ------
    const ull bw = ldv64(&g_bc[par][i]);             // cnt + sum in ONE load
    float4 sl0 = __ldcg(&g_slot[i * CAP + 0]);
    float4 sl1 = __ldcg(&g_slot[i * CAP + 1]);
    float4 sl2 = __ldcg(&g_slot[i * CAP + 2]);
    float4 sl3 = __ldcg(&g_slot[i * CAP + 3]);
    float csum0 = 0.0f, csum1 = 0.0f, csum2 = 0.0f, csum3 = 0.0f;
    if (w == 0) {   // warp 0 gathers all 128 chunk totals, 4 per lane
        csum0 = ldvf(&g_csum[par][(lane      ) * CSTRIDE]);
        csum1 = ldvf(&g_csum[par][(lane +  32) * CSTRIDE]);
        csum2 = ldvf(&g_csum[par][(lane +  64) * CSTRIDE]);
        csum3 = ldvf(&g_csum[par][(lane +  96) * CSTRIDE]);
    }
    const unsigned cnt = (unsigned)(bw >> 56);
    const float    bs  = (float)(bw & ((1ULL << 56) - 1ULL)) * E_INV;

    // Next-epoch zeroing — post-barrier, off the critical path.
    g_bc[par ^ 1][i] = 0ULL;
    if (t == 0) {
        g_csum[par ^ 1][blk * CSTRIDE] = 0.0f;
        if (blk == 0) g_acc[par ^ 1] = 0ULL;
    }

    // In-warp inclusive suffix scan of bucket sums
    float v = bs;
    #pragma unroll
    for (int d = 1; d < 32; d <<= 1) {
        float o = __shfl_down_sync(0xffffffffu, v, d);
        if (lane + d < 32) v += o;
    }
    if (lane == 0) s_w[w] = v;                       // warp total
    // Cross-chunk base: sum of chunk totals for chunks > blk (no barrier)
    if (w == 0) {
        float th = 0.0f;
        if ((lane      ) > blk) th += csum0;
        if ((lane +  32) > blk) th += csum1;
        if ((lane +  64) > blk) th += csum2;
        if ((lane +  96) > blk) th += csum3;
        #pragma unroll
        for (int o = 16; o > 0; o >>= 1) th += __shfl_down_sync(0xffffffffu, th, o);
        if (lane == 0) s_base = th;
    }
    __syncthreads();
    float hiW = 0.0f;
    #pragma unroll
    for (int k = 0; k < 4; k++) if (k > w) hiW += s_w[k];
    const float sb = s_base + (v - bs) + hiW;        // sum over buckets strictly > i

    // ---- Phase 3: per-element loss for my bucket (exact in-bucket ties) ---
    float num = 0.0f, den = 0.0f;
    if (cnt <= 4u) {                                 // register fast path (99.6%)
        const int len = (int)cnt;
        float tt[4] = {sl0.x, sl1.x, sl2.x, sl3.x};
        float ee[4] = {sl0.y, sl1.y, sl2.y, sl3.y};
        float vv[4] = {sl0.z, sl1.z, sl2.z, sl3.z};
        #pragma unroll
        for (int a = 0; a < 4; a++) {
            if (a < len && vv[a] != 0.0f) {
                float s = sb;
                #pragma unroll
                for (int m = 0; m < 4; m++)
                    if (m < len && tt[m] >= tt[a]) s += ee[m];
                num += __logf(ee[a] / s);            // = theta - log s
                den += 1.0f;
            }
        }
    } else if (cnt <= CAP) {                         // gmem path (rare, exact)
        const int len = (int)cnt;
        for (int a = 0; a < len; a++) {
            float4 pa = __ldcg(&g_slot[i * CAP + a]);
            if (pa.z != 0.0f) {
                float s = sb;
                for (int m = 0; m < len; m++) {
                    float4 pm = __ldcg(&g_slot[i * CAP + m]);
                    if (pm.x >= pa.x) s += pm.y;
                }
                num += __logf(pa.y / s);
                den += 1.0f;
            }
        }
    } else {                                         // overflow fallback (exact, ~never)
        for (int j = 0; j < NELEM; j++) {
            float tj = __ldg(&time[j]);
            if (bucket_of(tj) == i && __ldg(&event[j]) != 0.0f) {
                float s = sb;
                for (int m2 = 0; m2 < NELEM; m2++) {
                    float tm = __ldg(&time[m2]);
                    if (bucket_of(tm) == i && tm >= tj) s += __expf(__ldg(&risk[m2]));
                }
                num += __ldg(&risk[j]) - __logf(s);
                den += 1.0f;
            }
        }
    }

    // ---- Block reduce -> ONE fused atomic; last arriver owns the total ----
    #pragma unroll
    for (int o = 16; o > 0; o >>= 1) {
        num += __shfl_down_sync(0xffffffffu, num, o);
        den += __shfl_down_sync(0xffffffffu, den, o);
    }
    if (lane == 0) { rn[w] = num; rd[w] = den; }
    __syncthreads();
    if (t == 0) {
        float n = rn[0] + rn[1] + rn[2] + rn[3];
        float d = rd[0] + rd[1] + rd[2] + rd[3];
        // Pack: [63:56] arrival count, [55:41] den (integer), [40:0] biased num_fx.
        long long nfx = llrintf(n * NUM_SCALE);
        ull mine = (1ULL << 56)
                 | ((ull)(unsigned)(d + 0.5f) << 41)
                 | (ull)(nfx + NUM_BIAS);
        ull o2 = atomicAdd(&g_acc[par], mine);
        ull tot = o2 + mine;
        if ((tot >> 56) == (ull)NBLK) {              // I'm the last arriver
            long long tfx = (long long)(tot & ((1ULL << 41) - 1ULL))
                          - (long long)NBLK * NUM_BIAS;
            float tn = (float)tfx * (1.0f / NUM_SCALE);
            float td = (float)((tot >> 41) & 0x7FFFULL);
            out[0] = -tn / td;
            atomicAdd(&g_done, 1ULL);                // bump epoch (once per launch)
        }
    }
}

extern "C" void kernel_launch(void* const* d_in, const int* in_sizes, int n_in,
                              void* d_out, int out_size) {
    const float* risk  = (const float*)d_in[0];
    const float* time  = (const float*)d_in[1];
    const float* event = (const float*)d_in[2];
    float* out = (float*)d_out;
    cox_kernel<<<NBLK, NTHR>>>(risk, time, event, out);
}

// round 16
// speedup vs baseline: 1.5814x; 1.3692x over previous
#include <cuda_runtime.h>
#include <math.h>

#define NELEM 16384
#define NB    16384
#define NBLK  128
#define NTHR  128
#define CAP   16
#define CSTRIDE 64            // 256B between chunk counters (distinct L2 slices)
#define NUM_SCALE 262144.0f   // 2^18 fixed-point scale for num
#define NUM_BIAS  (1LL << 31) // per-block bias so contributions are positive

typedef unsigned long long ull;

// Parity-double-buffered / monotone scratch: replay-safe, no cleanup barrier.
__device__ float    g_bsum[2][NB];             // bucket sums (atomicAdd) — proven bulk path
__device__ unsigned g_cnt[2][NB];              // bucket slot counts (atomicAdd)
__device__ float4   g_slot[NB * CAP];          // (time, exp, event, 0) — tie lists only
__device__ float    g_csum[2][NBLK * CSTRIDE]; // chunk totals (atomicAdd, padded)
__device__ ull      g_acc[2];                  // fused tail: count|den|biased num (parity)
__device__ ull      g_bar;                     // monotone barrier counter: +NBLK per launch
__device__ ull      g_done;                    // epoch counter: +1 per launch (winner only)

static __device__ __forceinline__ ull ldv64(const ull* p) {
    ull v; asm volatile("ld.global.cg.u64 %0, [%1];" : "=l"(v) : "l"(p)); return v;
}
static __device__ __forceinline__ unsigned ldv32(const unsigned* p) {
    unsigned v; asm volatile("ld.global.cg.u32 %0, [%1];" : "=r"(v) : "l"(p)); return v;
}
static __device__ __forceinline__ float ldvf(const float* p) {
    float v; asm volatile("ld.global.cg.f32 %0, [%1];" : "=f"(v) : "l"(p)); return v;
}

static __device__ __forceinline__ int bucket_of(float t) {
    int b = (int)(t * 16384.0f);
    return b < 0 ? 0 : (b > NB - 1 ? NB - 1 : b);
}

__global__ void __launch_bounds__(NTHR, 1) cox_kernel(
    const float* __restrict__ risk,
    const float* __restrict__ time,
    const float* __restrict__ event,
    float* __restrict__ out)
{
    const int t   = threadIdx.x;
    const int blk = blockIdx.x;
    const int i   = blk * NTHR + t;
    const int lane = t & 31, w = t >> 5;

    __shared__ float s_w[4];
    __shared__ float s_base;
    __shared__ float rn[4], rd[4];

    // ---- Front: quiescent epoch + inputs, all loads concurrent ------------
    const unsigned ep1 = (unsigned)ldv64(&g_done) + 1u;
    const int par = (int)(ep1 & 1u);
    const float my_t  = __ldg(&time[i]);
    const float my_ev = __ldg(&event[i]);
    const float my_e  = __expf(__ldg(&risk[i]));     // MUFU-direct
    const int   b     = bucket_of(my_t);

    // ---- Phase 1: histogram + chunk totals + slot scatter (all atomic) ----
    unsigned c = atomicAdd(&g_cnt[par][b], 1u);      // issue first: return gates slot store
    atomicAdd(&g_bsum[par][b], my_e);                // exact bucket sum (proven path)
    atomicAdd(&g_csum[par][(b >> 7) * CSTRIDE], my_e); // chunk total, final pre-B1
    if (c < CAP) g_slot[b * CAP + c] = make_float4(my_t, my_e, my_ev, 0.0f);

    // ---- B1: monotone-counter grid barrier (R13-proven) --------------------
    __threadfence();                                  // drain slot store + atomics
    __syncthreads();
    if (t == 0) {
        atomicAdd(&g_bar, 1ULL);
        const ull target = (ull)ep1 * (ull)NBLK;
        while (ldv64(&g_bar) < target) { }
        __threadfence();
    }
    __syncthreads();

    // ---- Phase 2: owner of bucket i; ALL loads issued up front (MLP) ------
    const float    bs  = ldvf(&g_bsum[par][i]);
    const unsigned cnt = ldv32(&g_cnt[par][i]);
    float4 sl0 = __ldcg(&g_slot[i * CAP + 0]);
    float4 sl1 = __ldcg(&g_slot[i * CAP + 1]);
    float4 sl2 = __ldcg(&g_slot[i * CAP + 2]);
    float4 sl3 = __ldcg(&g_slot[i * CAP + 3]);
    float4 sl4 = __ldcg(&g_slot[i * CAP + 4]);
    float4 sl5 = __ldcg(&g_slot[i * CAP + 5]);
    float4 sl6 = __ldcg(&g_slot[i * CAP + 6]);
    float4 sl7 = __ldcg(&g_slot[i * CAP + 7]);
    float csum0 = 0.0f, csum1 = 0.0f, csum2 = 0.0f, csum3 = 0.0f;
    if (w == 0) {   // warp 0 gathers all 128 chunk totals, 4 per lane
        csum0 = ldvf(&g_csum[par][(lane      ) * CSTRIDE]);
        csum1 = ldvf(&g_csum[par][(lane +  32) * CSTRIDE]);
        csum2 = ldvf(&g_csum[par][(lane +  64) * CSTRIDE]);
        csum3 = ldvf(&g_csum[par][(lane +  96) * CSTRIDE]);
    }

    // Next-epoch zeroing — post-barrier, off the critical path.
    g_bsum[par ^ 1][i] = 0.0f;
    g_cnt[par ^ 1][i]  = 0u;
    if (t == 0) {
        g_csum[par ^ 1][blk * CSTRIDE] = 0.0f;
        if (blk == 0) g_acc[par ^ 1] = 0ULL;
    }

    // In-warp inclusive suffix scan of bucket sums
    float v = bs;
    #pragma unroll
    for (int d = 1; d < 32; d <<= 1) {
        float o = __shfl_down_sync(0xffffffffu, v, d);
        if (lane + d < 32) v += o;
    }
    if (lane == 0) s_w[w] = v;                       // warp total
    // Cross-chunk base: sum of chunk totals for chunks > blk (no barrier)
    if (w == 0) {
        float th = 0.0f;
        if ((lane      ) > blk) th += csum0;
        if ((lane +  32) > blk) th += csum1;
        if ((lane +  64) > blk) th += csum2;
        if ((lane +  96) > blk) th += csum3;
        #pragma unroll
        for (int o = 16; o > 0; o >>= 1) th += __shfl_down_sync(0xffffffffu, th, o);
        if (lane == 0) s_base = th;
    }
    __syncthreads();
    float hiW = 0.0f;
    #pragma unroll
    for (int k = 0; k < 4; k++) if (k > w) hiW += s_w[k];
    const float sb = s_base + (v - bs) + hiW;        // sum over buckets strictly > i

    // ---- Phase 3: per-element loss for my bucket (exact in-bucket ties) ---
    float num = 0.0f, den = 0.0f;
    if (cnt <= 8u) {                                 // register fast path (~99.9998%)
        const int len = (int)cnt;
        float tt[8] = {sl0.x, sl1.x, sl2.x, sl3.x, sl4.x, sl5.x, sl6.x, sl7.x};
        float ee[8] = {sl0.y, sl1.y, sl2.y, sl3.y, sl4.y, sl5.y, sl6.y, sl7.y};
        float vv[8] = {sl0.z, sl1.z, sl2.z, sl3.z, sl4.z, sl5.z, sl6.z, sl7.z};
        #pragma unroll
        for (int a = 0; a < 8; a++) {
            if (a < len && vv[a] != 0.0f) {
                float s = sb;
                #pragma unroll
                for (int m = 0; m < 8; m++)
                    if (m < len && tt[m] >= tt[a]) s += ee[m];
                num += __logf(ee[a] / s);            // = theta - log s
                den += 1.0f;
            }
        }
    } else if (cnt <= CAP) {                         // gmem path (now truly rare)
        const int len = (int)cnt;
        for (int a = 0; a < len; a++) {
            float4 pa = __ldcg(&g_slot[i * CAP + a]);
            if (pa.z != 0.0f) {
                float s = sb;
                for (int m = 0; m < len; m++) {
                    float4 pm = __ldcg(&g_slot[i * CAP + m]);
                    if (pm.x >= pa.x) s += pm.y;
                }
                num += __logf(pa.y / s);
                den += 1.0f;
            }
        }
    } else {                                         // overflow fallback (exact, ~never)
        for (int j = 0; j < NELEM; j++) {
            float tj = __ldg(&time[j]);
            if (bucket_of(tj) == i && __ldg(&event[j]) != 0.0f) {
                float s = sb;
                for (int m2 = 0; m2 < NELEM; m2++) {
                    float tm = __ldg(&time[m2]);
                    if (bucket_of(tm) == i && tm >= tj) s += __expf(__ldg(&risk[m2]));
                }
                num += __ldg(&risk[j]) - __logf(s);
                den += 1.0f;
            }
        }
    }

    // ---- Block reduce -> ONE fused atomic; last arriver owns the total ----
    #pragma unroll
    for (int o = 16; o > 0; o >>= 1) {
        num += __shfl_down_sync(0xffffffffu, num, o);
        den += __shfl_down_sync(0xffffffffu, den, o);
    }
    if (lane == 0) { rn[w] = num; rd[w] = den; }
    __syncthreads();
    if (t == 0) {
        float n = rn[0] + rn[1] + rn[2] + rn[3];
        float d = rd[0] + rd[1] + rd[2] + rd[3];
        // Pack: [63:56] arrival count, [55:41] den (integer), [40:0] biased num_fx.
        long long nfx = llrintf(n * NUM_SCALE);
        ull mine = (1ULL << 56)
                 | ((ull)(unsigned)(d + 0.5f) << 41)
                 | (ull)(nfx + NUM_BIAS);
        ull old = atomicAdd(&g_acc[par], mine);
        ull tot = old + mine;
        if ((tot >> 56) == (ull)NBLK) {              // I'm the last arriver
            long long tfx = (long long)(tot & ((1ULL << 41) - 1ULL))
                          - (long long)NBLK * NUM_BIAS;
            float tn = (float)tfx * (1.0f / NUM_SCALE);
            float td = (float)((tot >> 41) & 0x7FFFULL);
            out[0] = -tn / td;
            atomicAdd(&g_done, 1ULL);                // bump epoch (once per launch)
        }
    }
}

extern "C" void kernel_launch(void* const* d_in, const int* in_sizes, int n_in,
                              void* d_out, int out_size) {
    const float* risk  = (const float*)d_in[0];
    const float* time  = (const float*)d_in[1];
    const float* event = (const float*)d_in[2];
    float* out = (float*)d_out;
    cox_kernel<<<NBLK, NTHR>>>(risk, time, event, out);
}

// round 17
// speedup vs baseline: 1.6239x; 1.0269x over previous
#include <cuda_runtime.h>
#include <math.h>

#define NELEM 16384
#define NB    16384
#define NBLK  128
#define NTHR  128
#define CAP   16
#define CSTRIDE 64            // 256B between chunk counters (distinct L2 slices)
#define NUM_SCALE 262144.0f   // 2^18 fixed-point scale for num
#define NUM_BIAS  (1LL << 31) // per-block bias so contributions are positive

typedef unsigned long long ull;

// Parity-double-buffered / monotone scratch: replay-safe, no cleanup barrier.
__device__ float    g_bsum[2][NB];             // bucket sums (atomicAdd) — proven bulk path
__device__ unsigned g_cnt[2][NB];              // bucket slot counts (atomicAdd)
__device__ float4   g_slot[NB * CAP];          // (time, exp, event, 0) — tie lists only
__device__ float    g_csum[2][NBLK * CSTRIDE]; // chunk totals (atomicAdd, padded)
__device__ ull      g_acc[2];                  // fused tail: count|den|biased num (parity)
__device__ ull      g_bar;                     // monotone barrier counter: +NBLK per launch
__device__ ull      g_done;                    // epoch counter: +1 per launch (winner only)

static __device__ __forceinline__ ull ldv64(const ull* p) {
    ull v; asm volatile("ld.global.cg.u64 %0, [%1];" : "=l"(v) : "l"(p)); return v;
}
static __device__ __forceinline__ unsigned ldv32(const unsigned* p) {
    unsigned v; asm volatile("ld.global.cg.u32 %0, [%1];" : "=r"(v) : "l"(p)); return v;
}
static __device__ __forceinline__ float ldvf(const float* p) {
    float v; asm volatile("ld.global.cg.f32 %0, [%1];" : "=f"(v) : "l"(p)); return v;
}

static __device__ __forceinline__ int bucket_of(float t) {
    int b = (int)(t * 16384.0f);
    return b < 0 ? 0 : (b > NB - 1 ? NB - 1 : b);
}

__global__ void __launch_bounds__(NTHR, 1) cox_kernel(
    const float* __restrict__ risk,
    const float* __restrict__ time,
    const float* __restrict__ event,
    float* __restrict__ out)
{
    const int t   = threadIdx.x;
    const int blk = blockIdx.x;
    const int i   = blk * NTHR + t;
    const int lane = t & 31, w = t >> 5;

    __shared__ float s_w[4];
    __shared__ float s_base;
    __shared__ int   rn[4], rd[4];

    // ---- Front: quiescent epoch + inputs, all loads concurrent ------------
    const unsigned ep1 = (unsigned)ldv64(&g_done) + 1u;
    const int par = (int)(ep1 & 1u);
    const float my_t  = __ldg(&time[i]);
    const float my_ev = __ldg(&event[i]);
    const float my_e  = __expf(__ldg(&risk[i]));     // MUFU-direct
    const int   b     = bucket_of(my_t);

    // ---- Phase 1: histogram + chunk totals + slot scatter (all atomic) ----
    unsigned c = atomicAdd(&g_cnt[par][b], 1u);
    atomicAdd(&g_bsum[par][b], my_e);                // exact bucket sum (proven path)
    atomicAdd(&g_csum[par][(b >> 7) * CSTRIDE], my_e); // chunk total, final pre-B1
    if (c < CAP) g_slot[b * CAP + c] = make_float4(my_t, my_e, my_ev, 0.0f);

    // ---- B1: monotone-counter barrier; ALL threads poll (no release sync) --
    __threadfence();                                  // drain slot store + atomics
    __syncthreads();                                  // all block threads drained
    if (t == 0) atomicAdd(&g_bar, 1ULL);              // one arrival per block
    {
        const ull target = (ull)ep1 * (ull)NBLK;
        while (ldv64(&g_bar) < target) { }            // per-thread detect, no sync after
    }

    // ---- Phase 2: owner of bucket i; ALL loads issued up front (MLP) ------
    const float    bs  = ldvf(&g_bsum[par][i]);
    const unsigned cnt = ldv32(&g_cnt[par][i]);
    float4 sl0 = __ldcg(&g_slot[i * CAP + 0]);
    float4 sl1 = __ldcg(&g_slot[i * CAP + 1]);
    float4 sl2 = __ldcg(&g_slot[i * CAP + 2]);
    float4 sl3 = __ldcg(&g_slot[i * CAP + 3]);
    float4 sl4 = __ldcg(&g_slot[i * CAP + 4]);
    float4 sl5 = __ldcg(&g_slot[i * CAP + 5]);
    float4 sl6 = __ldcg(&g_slot[i * CAP + 6]);
    float4 sl7 = __ldcg(&g_slot[i * CAP + 7]);
    float csum0 = 0.0f, csum1 = 0.0f, csum2 = 0.0f, csum3 = 0.0f;
    if (w == 0) {   // warp 0 gathers all 128 chunk totals, 4 per lane
        csum0 = ldvf(&g_csum[par][(lane      ) * CSTRIDE]);
        csum1 = ldvf(&g_csum[par][(lane +  32) * CSTRIDE]);
        csum2 = ldvf(&g_csum[par][(lane +  64) * CSTRIDE]);
        csum3 = ldvf(&g_csum[par][(lane +  96) * CSTRIDE]);
    }

    // Next-epoch zeroing — off the critical path.
    g_bsum[par ^ 1][i] = 0.0f;
    g_cnt[par ^ 1][i]  = 0u;
    if (t == 0) {
        g_csum[par ^ 1][blk * CSTRIDE] = 0.0f;
        if (blk == 0) g_acc[par ^ 1] = 0ULL;
    }

    // In-warp inclusive suffix scan of bucket sums
    float v = bs;
    #pragma unroll
    for (int d = 1; d < 32; d <<= 1) {
        float o = __shfl_down_sync(0xffffffffu, v, d);
        if (lane + d < 32) v += o;
    }
    if (lane == 0) s_w[w] = v;                       // warp total
    // Cross-chunk base: sum of chunk totals for chunks > blk (no barrier)
    if (w == 0) {
        float th = 0.0f;
        if ((lane      ) > blk) th += csum0;
        if ((lane +  32) > blk) th += csum1;
        if ((lane +  64) > blk) th += csum2;
        if ((lane +  96) > blk) th += csum3;
        #pragma unroll
        for (int o = 16; o > 0; o >>= 1) th += __shfl_down_sync(0xffffffffu, th, o);
        if (lane == 0) s_base = th;
    }
    __syncthreads();
    float hiW = 0.0f;
    #pragma unroll
    for (int k = 0; k < 4; k++) if (k > w) hiW += s_w[k];
    const float sb = s_base + (v - bs) + hiW;        // sum over buckets strictly > i

    // ---- Phase 3: per-element loss for my bucket (exact in-bucket ties) ---
    float num = 0.0f;
    int   den = 0;
    if (cnt <= 8u) {                                 // register fast path (~99.9998%)
        const int len = (int)cnt;
        float tt[8] = {sl0.x, sl1.x, sl2.x, sl3.x, sl4.x, sl5.x, sl6.x, sl7.x};
        float ee[8] = {sl0.y, sl1.y, sl2.y, sl3.y, sl4.y, sl5.y, sl6.y, sl7.y};
        float vv[8] = {sl0.z, sl1.z, sl2.z, sl3.z, sl4.z, sl5.z, sl6.z, sl7.z};
        #pragma unroll
        for (int a = 0; a < 8; a++) {
            if (a < len && vv[a] != 0.0f) {
                float s = sb;
                #pragma unroll
                for (int m = 0; m < 8; m++)
                    if (m < len && tt[m] >= tt[a]) s += ee[m];
                num += __logf(ee[a] / s);            // = theta - log s
                den += 1;
            }
        }
    } else if (cnt <= CAP) {                         // gmem path (truly rare)
        const int len = (int)cnt;
        for (int a = 0; a < len; a++) {
            float4 pa = __ldcg(&g_slot[i * CAP + a]);
            if (pa.z != 0.0f) {
                float s = sb;
                for (int m = 0; m < len; m++) {
                    float4 pm = __ldcg(&g_slot[i * CAP + m]);
                    if (pm.x >= pa.x) s += pm.y;
                }
                num += __logf(pa.y / s);
                den += 1;
            }
        }
    } else {                                         // overflow fallback (exact, ~never)
        for (int j = 0; j < NELEM; j++) {
            float tj = __ldg(&time[j]);
            if (bucket_of(tj) == i && __ldg(&event[j]) != 0.0f) {
                float s = sb;
                for (int m2 = 0; m2 < NELEM; m2++) {
                    float tm = __ldg(&time[m2]);
                    if (bucket_of(tm) == i && tm >= tj) s += __expf(__ldg(&risk[m2]));
                }
                num += __ldg(&risk[j]) - __logf(s);
                den += 1;
            }
        }
    }

    // ---- Block reduce via integer REDUX -> ONE fused atomic ----------------
    int nfx32 = (int)llrintf(num * NUM_SCALE);       // |num| < 8000 -> fits s32 easily
    nfx32 = __reduce_add_sync(0xffffffffu, nfx32);   // REDUX.SUM, one op
    int dsum = __reduce_add_sync(0xffffffffu, den);
    if (lane == 0) { rn[w] = nfx32; rd[w] = dsum; }
    __syncthreads();
    if (t == 0) {
        long long nfx = (long long)(rn[0] + rn[1] + rn[2] + rn[3]);
        int       d   = rd[0] + rd[1] + rd[2] + rd[3];
        // Pack: [63:56] arrival count, [55:41] den (integer), [40:0] biased num_fx.
        ull mine = (1ULL << 56)
                 | ((ull)(unsigned)d << 41)
                 | (ull)(nfx + NUM_BIAS);
        ull old = atomicAdd(&g_acc[par], mine);
        ull tot = old + mine;
        if ((tot >> 56) == (ull)NBLK) {              // I'm the last arriver
            long long tfx = (long long)(tot & ((1ULL << 41) - 1ULL))
                          - (long long)NBLK * NUM_BIAS;
            float tn = (float)tfx * (1.0f / NUM_SCALE);
            float td = (float)((tot >> 41) & 0x7FFFULL);
            out[0] = -tn / td;
            atomicAdd(&g_done, 1ULL);                // bump epoch (once per launch)
        }
    }
}

extern "C" void kernel_launch(void* const* d_in, const int* in_sizes, int n_in,
                              void* d_out, int out_size) {
    const float* risk  = (const float*)d_in[0];
    const float* time  = (const float*)d_in[1];
    const float* event = (const float*)d_in[2];
    float* out = (float*)d_out;
    cox_kernel<<<NBLK, NTHR>>>(risk, time, event, out);
}